// round 10
// baseline (speedup 1.0000x reference)
#include <cuda_runtime.h>
#include <cuda_bf16.h>
#include <cstdint>

#define BBAT 4
#define TT 2048
#define DM 2048
#define NH 16
#define DH 128
#define MROWS (BBAT * TT)

// ---- scratch ----
__device__ __nv_bfloat16 g_xhi[(size_t)MROWS * DM], g_xlo[(size_t)MROWS * DM];
__device__ __nv_bfloat16 g_chi[(size_t)MROWS * DM], g_clo[(size_t)MROWS * DM];
__device__ __nv_bfloat16 g_qhi[(size_t)MROWS * DM], g_qlo[(size_t)MROWS * DM];
__device__ __nv_bfloat16 g_khi[(size_t)MROWS * DH], g_klo[(size_t)MROWS * DH];
__device__ __nv_bfloat16 g_vhi[(size_t)MROWS * DH], g_vlo[(size_t)MROWS * DH];
__device__ __nv_bfloat16 g_vthi[(size_t)DH * MROWS], g_vtlo[(size_t)DH * MROWS];
__device__ __nv_bfloat16 g_wqhi[(size_t)DM * DM], g_wqlo[(size_t)DM * DM];
__device__ __nv_bfloat16 g_wkhi[(size_t)DH * DM], g_wklo[(size_t)DH * DM];
__device__ __nv_bfloat16 g_wvhi[(size_t)DH * DM], g_wvlo[(size_t)DH * DM];
__device__ __nv_bfloat16 g_wohi[(size_t)DM * DM], g_wolo[(size_t)DM * DM];

// ---- PTX helpers ----
__device__ __forceinline__ uint32_t smem_u32(const void* p) {
    uint32_t a;
    asm("{ .reg .u64 t; cvta.to.shared.u64 t, %1; cvt.u32.u64 %0, t; }" : "=r"(a) : "l"(p));
    return a;
}
#define CP16(s, g) \
    asm volatile("cp.async.cg.shared.global [%0], [%1], 16;" :: "r"(s), "l"(g))
#define CP_COMMIT() asm volatile("cp.async.commit_group;" ::: "memory")
#define CP_WAIT1() asm volatile("cp.async.wait_group 1;" ::: "memory")
#define CP_WAIT0() asm volatile("cp.async.wait_group 0;" ::: "memory")

__device__ __forceinline__ void ldsm_x4(uint32_t& r0, uint32_t& r1, uint32_t& r2,
                                        uint32_t& r3, uint32_t addr) {
    asm volatile("ldmatrix.sync.aligned.m8n8.x4.shared.b16 {%0,%1,%2,%3}, [%4];"
                 : "=r"(r0), "=r"(r1), "=r"(r2), "=r"(r3) : "r"(addr));
}
__device__ __forceinline__ void mma16816(float* c, const uint32_t* a, const uint32_t* b) {
    asm volatile("mma.sync.aligned.m16n8k16.row.col.f32.bf16.bf16.f32 "
                 "{%0,%1,%2,%3}, {%4,%5,%6,%7}, {%8,%9}, {%0,%1,%2,%3};"
                 : "+f"(c[0]), "+f"(c[1]), "+f"(c[2]), "+f"(c[3])
                 : "r"(a[0]), "r"(a[1]), "r"(a[2]), "r"(a[3]), "r"(b[0]), "r"(b[1]));
}
__device__ __forceinline__ float ex2f(float x) {
    float y;
    asm("ex2.approx.f32 %0, %1;" : "=f"(y) : "f"(x));
    return y;
}

// ---- fp32 -> bf16 hi/lo ----
__device__ __forceinline__ void split1(float v, __nv_bfloat16& h, __nv_bfloat16& l) {
    h = __float2bfloat16(v);
    l = __float2bfloat16(v - __bfloat162float(h));
}
__device__ __forceinline__ uint32_t pk2(__nv_bfloat16 a, __nv_bfloat16 b) {
    return (uint32_t)__bfloat16_as_ushort(a) | ((uint32_t)__bfloat16_as_ushort(b) << 16);
}
__device__ __forceinline__ uint32_t splitpk_hi(float a, float b) {
    return pk2(__float2bfloat16(a), __float2bfloat16(b));
}
__device__ __forceinline__ uint32_t splitpk_lo(float a, float b) {
    __nv_bfloat16 ha = __float2bfloat16(a), hb = __float2bfloat16(b);
    return pk2(__float2bfloat16(a - __bfloat162float(ha)),
               __float2bfloat16(b - __bfloat162float(hb)));
}

// ============================================================
// Fused prep (unchanged, validated)
// ============================================================
__device__ __forceinline__ void do_tsplit(const float* __restrict__ W,
                                          __nv_bfloat16* hi, __nv_bfloat16* lo,
                                          int Kd, int Nd, int bx2,
                                          float (*t)[33]) {
    const int xw = Nd / 32;
    const int nb = (bx2 % xw) * 32, kb = (bx2 / xw) * 32;
    const int tx = threadIdx.x & 31, ty = threadIdx.x >> 5;
#pragma unroll
    for (int i = 0; i < 4; i++)
        t[ty + 8 * i][tx] = W[(size_t)(kb + ty + 8 * i) * Nd + nb + tx];
    __syncthreads();
#pragma unroll
    for (int i = 0; i < 4; i++) {
        const int nrow = ty + 8 * i;
        __nv_bfloat16 h, l;
        split1(t[tx][nrow], h, l);
        const size_t o = (size_t)(nb + nrow) * Kd + kb + tx;
        hi[o] = h; lo[o] = l;
    }
}

__global__ __launch_bounds__(256) void prep_kernel(
    const float* __restrict__ x, const float* __restrict__ Wq,
    const float* __restrict__ Wk, const float* __restrict__ Wv,
    const float* __restrict__ Wo)
{
    __shared__ float t[32][33];
    const int bx = blockIdx.x;
    if (bx < 4096) {
        const int n4 = MROWS * DM / 4;
        for (int i = bx * 256 + threadIdx.x; i < n4; i += 4096 * 256) {
            float4 v = ((const float4*)x)[i];
            __nv_bfloat16 h0, h1, h2, h3, l0, l1, l2, l3;
            split1(v.x, h0, l0); split1(v.y, h1, l1);
            split1(v.z, h2, l2); split1(v.w, h3, l3);
            uint2 H, L;
            H.x = pk2(h0, h1); H.y = pk2(h2, h3);
            L.x = pk2(l0, l1); L.y = pk2(l2, l3);
            ((uint2*)g_xhi)[i] = H;
            ((uint2*)g_xlo)[i] = L;
        }
    } else if (bx < 8192) {
        do_tsplit(Wq, g_wqhi, g_wqlo, DM, DM, bx - 4096, t);
    } else if (bx < 8448) {
        do_tsplit(Wk, g_wkhi, g_wklo, DM, DH, bx - 8192, t);
    } else if (bx < 8704) {
        do_tsplit(Wv, g_wvhi, g_wvlo, DM, DH, bx - 8448, t);
    } else {
        do_tsplit(Wo, g_wohi, g_wolo, DM, DM, bx - 8704, t);
    }
}

__global__ __launch_bounds__(256) void vt_kernel() {
    __shared__ __nv_bfloat16 th[32][34], tl[32][34];
    const int b = blockIdx.z, d0 = blockIdx.y * 32, t0 = blockIdx.x * 32;
    const int tx = threadIdx.x & 31, ty = threadIdx.x >> 5;
#pragma unroll
    for (int i = 0; i < 4; i++) {
        const int row = ty + 8 * i;
        const size_t gsrc = (size_t)(b * TT + t0 + row) * DH + d0 + tx;
        th[row][tx] = g_vhi[gsrc];
        tl[row][tx] = g_vlo[gsrc];
    }
    __syncthreads();
#pragma unroll
    for (int i = 0; i < 4; i++) {
        const int drow = ty + 8 * i;
        const size_t gdst = ((size_t)b * DH + d0 + drow) * TT + t0 + tx;
        g_vthi[gdst] = th[tx][drow];
        g_vtlo[gdst] = tl[tx][drow];
    }
}

// ============================================================
// mma.sync bf16x3 GEMM (unchanged, validated)
// ============================================================
#define STG 40960
#define OAH 0
#define OAL 10240
#define OBH 20480
#define OBL 30720

__global__ __launch_bounds__(256, 2) void tc_gemm(
    const float* __restrict__ b0, const float* __restrict__ b1,
    const float* __restrict__ b2, float* __restrict__ Cext,
    int asel, int fused)
{
    extern __shared__ char sm[];
    const uint32_t sbase = smem_u32(sm);
    const int tid = threadIdx.x;
    const int lane = tid & 31, warp = tid >> 5;
    const int wm = warp & 3, wn = warp >> 2;
    const int bx = blockIdx.x;
    const int rowBase = blockIdx.y * 128;

    const __nv_bfloat16* Ahi = asel ? g_chi : g_xhi;
    const __nv_bfloat16* Alo = asel ? g_clo : g_xlo;
    const __nv_bfloat16 *Bhi, *Blo;
    int wRow0;
    if (fused) {
        if (bx < 16)       { Bhi = g_wqhi; Blo = g_wqlo; wRow0 = bx * 128; }
        else if (bx == 16) { Bhi = g_wkhi; Blo = g_wklo; wRow0 = 0; }
        else               { Bhi = g_wvhi; Blo = g_wvlo; wRow0 = 0; }
    } else                 { Bhi = g_wohi; Blo = g_wolo; wRow0 = bx * 128; }

    float acc[2][8][4];
#pragma unroll
    for (int mt = 0; mt < 2; mt++)
#pragma unroll
        for (int nt = 0; nt < 8; nt++)
#pragma unroll
            for (int e = 0; e < 4; e++) acc[mt][nt][e] = 0.f;

    const int lr = tid >> 2, lc = tid & 3;
    const int a_r = lane & 15;
    const uint32_t a_kb = (lane & 16) ? 16 : 0;
    const int b_n = (lane & 7) + ((lane & 16) ? 8 : 0);
    const uint32_t b_kb = (lane & 8) ? 16 : 0;

#define LOAD_STAGE(buf, k0) do { \
    const uint32_t sb_ = sbase + (buf) * STG; \
    _Pragma("unroll") \
    for (int h_ = 0; h_ < 2; h_++) { \
        const int r_ = lr + h_ * 64; \
        const uint32_t so_ = r_ * 80 + lc * 16; \
        const size_t ga_ = (size_t)(rowBase + r_) * DM + (k0) + lc * 8; \
        const size_t gb_ = (size_t)(wRow0 + r_) * DM + (k0) + lc * 8; \
        CP16(sb_ + OAH + so_, Ahi + ga_); \
        CP16(sb_ + OAL + so_, Alo + ga_); \
        CP16(sb_ + OBH + so_, Bhi + gb_); \
        CP16(sb_ + OBL + so_, Blo + gb_); \
    } \
} while (0)

    LOAD_STAGE(0, 0);
    CP_COMMIT();

    const int ITERS = DM / 32;
    for (int s = 0; s < ITERS; s++) {
        if (s + 1 < ITERS) { LOAD_STAGE((s + 1) & 1, (s + 1) * 32); CP_COMMIT(); CP_WAIT1(); }
        else               { CP_WAIT0(); }
        __syncthreads();

        const uint32_t sb = sbase + (s & 1) * STG;
#pragma unroll
        for (int ks = 0; ks < 2; ks++) {
            const uint32_t kso = ks * 32;
            uint32_t ah[2][4], bb[8][2];
#pragma unroll
            for (int mt = 0; mt < 2; mt++) {
                const uint32_t addr = sb + OAH + (wm * 32 + mt * 16 + a_r) * 80 + kso + a_kb;
                ldsm_x4(ah[mt][0], ah[mt][1], ah[mt][2], ah[mt][3], addr);
            }
#pragma unroll
            for (int p = 0; p < 4; p++) {
                const uint32_t addr = sb + OBH + (wn * 64 + p * 16 + b_n) * 80 + kso + b_kb;
                ldsm_x4(bb[p * 2][0], bb[p * 2][1], bb[p * 2 + 1][0], bb[p * 2 + 1][1], addr);
            }
#pragma unroll
            for (int mt = 0; mt < 2; mt++)
#pragma unroll
                for (int nt = 0; nt < 8; nt++)
                    mma16816(acc[mt][nt], ah[mt], bb[nt]);
            {
                uint32_t al[2][4];
#pragma unroll
                for (int mt = 0; mt < 2; mt++) {
                    const uint32_t addr = sb + OAL + (wm * 32 + mt * 16 + a_r) * 80 + kso + a_kb;
                    ldsm_x4(al[mt][0], al[mt][1], al[mt][2], al[mt][3], addr);
                }
#pragma unroll
                for (int mt = 0; mt < 2; mt++)
#pragma unroll
                    for (int nt = 0; nt < 8; nt++)
                        mma16816(acc[mt][nt], al[mt], bb[nt]);
            }
#pragma unroll
            for (int p = 0; p < 4; p++) {
                const uint32_t addr = sb + OBL + (wn * 64 + p * 16 + b_n) * 80 + kso + b_kb;
                ldsm_x4(bb[p * 2][0], bb[p * 2][1], bb[p * 2 + 1][0], bb[p * 2 + 1][1], addr);
            }
#pragma unroll
            for (int mt = 0; mt < 2; mt++)
#pragma unroll
                for (int nt = 0; nt < 8; nt++)
                    mma16816(acc[mt][nt], ah[mt], bb[nt]);
        }
        __syncthreads();
    }

    const int g = lane >> 2, t2 = lane & 3;
    if (!fused) {
#pragma unroll
        for (int mt = 0; mt < 2; mt++) {
            const int r0 = rowBase + wm * 32 + mt * 16 + g;
#pragma unroll
            for (int nt = 0; nt < 8; nt++) {
                const int col = bx * 128 + wn * 64 + nt * 8 + t2 * 2;
                const float bxv = b0[col], byv = b0[col + 1];
                float2 o0, o1;
                o0.x = acc[mt][nt][0] + bxv; o0.y = acc[mt][nt][1] + byv;
                o1.x = acc[mt][nt][2] + bxv; o1.y = acc[mt][nt][3] + byv;
                *(float2*)(Cext + (size_t)r0 * DM + col) = o0;
                *(float2*)(Cext + (size_t)(r0 + 8) * DM + col) = o1;
            }
        }
    } else if (bx < 16) {
#pragma unroll
        for (int mt = 0; mt < 2; mt++) {
            const int r0 = rowBase + wm * 32 + mt * 16 + g;
#pragma unroll
            for (int nt = 0; nt < 8; nt++) {
                const int col = bx * 128 + wn * 64 + nt * 8 + t2 * 2;
                const float bxv = b0[col], byv = b0[col + 1];
                const float v0 = acc[mt][nt][0] + bxv, v1 = acc[mt][nt][1] + byv;
                const float v2 = acc[mt][nt][2] + bxv, v3 = acc[mt][nt][3] + byv;
                *(uint32_t*)&g_qhi[(size_t)r0 * DM + col] = splitpk_hi(v0, v1);
                *(uint32_t*)&g_qlo[(size_t)r0 * DM + col] = splitpk_lo(v0, v1);
                *(uint32_t*)&g_qhi[(size_t)(r0 + 8) * DM + col] = splitpk_hi(v2, v3);
                *(uint32_t*)&g_qlo[(size_t)(r0 + 8) * DM + col] = splitpk_lo(v2, v3);
            }
        }
    } else {
        __nv_bfloat16* Dh = (bx == 16) ? g_khi : g_vhi;
        __nv_bfloat16* Dl = (bx == 16) ? g_klo : g_vlo;
        const float* bb2 = (bx == 16) ? b1 : b2;
#pragma unroll
        for (int mt = 0; mt < 2; mt++) {
            const int r0 = rowBase + wm * 32 + mt * 16 + g;
#pragma unroll
            for (int nt = 0; nt < 8; nt++) {
                const int col = wn * 64 + nt * 8 + t2 * 2;
                const float bxv = bb2[col], byv = bb2[col + 1];
                const float v0 = acc[mt][nt][0] + bxv, v1 = acc[mt][nt][1] + byv;
                const float v2 = acc[mt][nt][2] + bxv, v3 = acc[mt][nt][3] + byv;
                *(uint32_t*)&Dh[(size_t)r0 * DH + col] = splitpk_hi(v0, v1);
                *(uint32_t*)&Dl[(size_t)r0 * DH + col] = splitpk_lo(v0, v1);
                *(uint32_t*)&Dh[(size_t)(r0 + 8) * DH + col] = splitpk_hi(v2, v3);
                *(uint32_t*)&Dl[(size_t)(r0 + 8) * DH + col] = splitpk_lo(v2, v3);
            }
        }
    }
}

// ============================================================
// Flash attention v2: 128-thread CTAs (4 warps, 64 q-rows),
// BN=32 KV tiles, 2-stage prefetch, 2 CTAs/SM for phase overlap.
// smem: Q hi/lo [0,34816); stage s @ 34816 + s*37888:
//   Khi +0 (32x272), Klo +8704, Vthi +17408 (128x80), Vtlo +27648
// ============================================================
#define AQS 272
#define AVS 80
#define QREG 34816
#define SKV 37888
#define ASMEM (QREG + 2 * SKV)   // 110592

__global__ __launch_bounds__(128, 2) void attn_mma()
{
    extern __shared__ char sm[];
    const uint32_t sb0 = smem_u32(sm);
    const int qt = gridDim.x - 1 - blockIdx.x;   // heavy tiles first
    const int h = blockIdx.y, b = blockIdx.z;
    const int tid = threadIdx.x, lane = tid & 31, w = tid >> 5;   // w: 0..3
    const int g = lane >> 2, t2 = lane & 3;
    const int a_r = lane & 15;
    const uint32_t a_kb = (lane & 16) ? 16 : 0;
    const int b_n = (lane & 7) + ((lane & 16) ? 8 : 0);
    const uint32_t b_kb = (lane & 8) ? 16 : 0;

    // --- Q (64 rows x 128) into dedicated region, then hoist ---
    {
        const size_t qbase = (size_t)(b * TT + qt * 64) * DM + h * DH;
#pragma unroll
        for (int j = 0; j < 8; j++) {
            const int n = tid + j * 128;
            const int row = n >> 4, ch = n & 15;
            const size_t gq = qbase + (size_t)row * DM + ch * 8;
            CP16(sb0 + row * AQS + ch * 16, g_qhi + gq);
            CP16(sb0 + 17408 + row * AQS + ch * 16, g_qlo + gq);
        }
    }
    CP_COMMIT();
    CP_WAIT0();
    __syncthreads();

    uint32_t aQh[8][4], aQl[8][4];
#pragma unroll
    for (int kt = 0; kt < 8; kt++) {
        const uint32_t qaddr = sb0 + (w * 16 + a_r) * AQS + kt * 32 + a_kb;
        ldsm_x4(aQh[kt][0], aQh[kt][1], aQh[kt][2], aQh[kt][3], qaddr);
        ldsm_x4(aQl[kt][0], aQl[kt][1], aQl[kt][2], aQl[kt][3], qaddr + 17408);
    }
    // Q region is dedicated (never overwritten) — no extra sync needed.

#define LOADKV(buf, kb) do { \
    const uint32_t kvb_ = sb0 + QREG + (buf) * SKV; \
    const size_t kbase_ = (size_t)(b * TT + (kb) * 32) * DH; \
    const size_t vbase_ = (size_t)b * DH * TT + (size_t)(kb) * 32; \
    _Pragma("unroll") \
    for (int j_ = 0; j_ < 4; j_++) { \
        const int n_ = tid + j_ * 128; \
        const int kr_ = n_ >> 4, kc_ = n_ & 15; \
        const size_t gk_ = kbase_ + (size_t)kr_ * DH + kc_ * 8; \
        CP16(kvb_ + kr_ * AQS + kc_ * 16, g_khi + gk_); \
        CP16(kvb_ + 8704 + kr_ * AQS + kc_ * 16, g_klo + gk_); \
        const int vr_ = n_ >> 2, vc_ = n_ & 3; \
        const size_t gv_ = vbase_ + (size_t)vr_ * TT + vc_ * 8; \
        CP16(kvb_ + 17408 + vr_ * AVS + vc_ * 16, g_vthi + gv_); \
        CP16(kvb_ + 27648 + vr_ * AVS + vc_ * 16, g_vtlo + gv_); \
    } \
} while (0)

    const int ntiles = 2 * qt + 2;   // 32-col KV tiles
    LOADKV(0, 0);
    CP_COMMIT();

    float O[16][4];
#pragma unroll
    for (int i = 0; i < 16; i++)
#pragma unroll
        for (int e = 0; e < 4; e++) O[i][e] = 0.f;
    float m0 = -1e30f, m1 = -1e30f, l0 = 0.f, l1 = 0.f;
    // scale * log2(e): logits kept in log2 domain; exp -> ex2
    const float sc2 = 0.08838834764831845f * 1.4426950408889634f;
    const int qrow0 = qt * 64 + w * 16 + g;
    const int wrow_max = qt * 64 + w * 16 + 15;   // warp-uniform

    for (int it = 0; it < ntiles; it++) {
        if (it + 1 < ntiles) { LOADKV((it + 1) & 1, it + 1); CP_COMMIT(); CP_WAIT1(); }
        else                 { CP_WAIT0(); }
        __syncthreads();
        const uint32_t kvb = sb0 + QREG + (it & 1) * SKV;

        if (it * 32 <= wrow_max) {   // skip fully-masked diagonal tiles (warp-uniform)
            // ---- S = Q K^T (x3) ----
            float sS[4][4];
#pragma unroll
            for (int i = 0; i < 4; i++)
#pragma unroll
                for (int e = 0; e < 4; e++) sS[i][e] = 0.f;
#pragma unroll
            for (int kt = 0; kt < 8; kt++) {
#pragma unroll
                for (int p = 0; p < 2; p++) {
                    const uint32_t kaddr = kvb + (p * 16 + b_n) * AQS + kt * 32 + b_kb;
                    uint32_t bh0[2], bh1[2], bl0[2], bl1[2];
                    ldsm_x4(bh0[0], bh0[1], bh1[0], bh1[1], kaddr);
                    ldsm_x4(bl0[0], bl0[1], bl1[0], bl1[1], kaddr + 8704);
                    mma16816(sS[2 * p], aQh[kt], bh0);
                    mma16816(sS[2 * p + 1], aQh[kt], bh1);
                    mma16816(sS[2 * p], aQl[kt], bh0);
                    mma16816(sS[2 * p + 1], aQl[kt], bh1);
                    mma16816(sS[2 * p], aQh[kt], bl0);
                    mma16816(sS[2 * p + 1], aQh[kt], bl1);
                }
            }

            // ---- online softmax (log2 domain) ----
            const int kcol0 = it * 32 + 2 * t2;
            float ml0 = -1e30f, ml1 = -1e30f;
#pragma unroll
            for (int nt = 0; nt < 4; nt++) {
                const int c = kcol0 + nt * 8;
                float s0 = sS[nt][0] * sc2, s1 = sS[nt][1] * sc2;
                float s2 = sS[nt][2] * sc2, s3 = sS[nt][3] * sc2;
                if (c > qrow0)         s0 = -1e30f;
                if (c + 1 > qrow0)     s1 = -1e30f;
                if (c > qrow0 + 8)     s2 = -1e30f;
                if (c + 1 > qrow0 + 8) s3 = -1e30f;
                sS[nt][0] = s0; sS[nt][1] = s1; sS[nt][2] = s2; sS[nt][3] = s3;
                ml0 = fmaxf(ml0, fmaxf(s0, s1));
                ml1 = fmaxf(ml1, fmaxf(s2, s3));
            }
            ml0 = fmaxf(ml0, __shfl_xor_sync(0xffffffffu, ml0, 1));
            ml0 = fmaxf(ml0, __shfl_xor_sync(0xffffffffu, ml0, 2));
            ml1 = fmaxf(ml1, __shfl_xor_sync(0xffffffffu, ml1, 1));
            ml1 = fmaxf(ml1, __shfl_xor_sync(0xffffffffu, ml1, 2));
            const float mn0 = fmaxf(m0, ml0), mn1 = fmaxf(m1, ml1);
            const float al0 = ex2f(m0 - mn0), al1 = ex2f(m1 - mn1);

            float ps0 = 0.f, ps1 = 0.f;
            uint32_t aPh[2][4], aPl[2][4];
#pragma unroll
            for (int u = 0; u < 2; u++) {
                const float p00 = ex2f(sS[2 * u][0] - mn0);
                const float p01 = ex2f(sS[2 * u][1] - mn0);
                const float p02 = ex2f(sS[2 * u][2] - mn1);
                const float p03 = ex2f(sS[2 * u][3] - mn1);
                const float p10 = ex2f(sS[2 * u + 1][0] - mn0);
                const float p11 = ex2f(sS[2 * u + 1][1] - mn0);
                const float p12 = ex2f(sS[2 * u + 1][2] - mn1);
                const float p13 = ex2f(sS[2 * u + 1][3] - mn1);
                ps0 += p00 + p01 + p10 + p11;
                ps1 += p02 + p03 + p12 + p13;
                aPh[u][0] = splitpk_hi(p00, p01); aPl[u][0] = splitpk_lo(p00, p01);
                aPh[u][1] = splitpk_hi(p02, p03); aPl[u][1] = splitpk_lo(p02, p03);
                aPh[u][2] = splitpk_hi(p10, p11); aPl[u][2] = splitpk_lo(p10, p11);
                aPh[u][3] = splitpk_hi(p12, p13); aPl[u][3] = splitpk_lo(p12, p13);
            }
            ps0 += __shfl_xor_sync(0xffffffffu, ps0, 1);
            ps0 += __shfl_xor_sync(0xffffffffu, ps0, 2);
            ps1 += __shfl_xor_sync(0xffffffffu, ps1, 1);
            ps1 += __shfl_xor_sync(0xffffffffu, ps1, 2);
            l0 = l0 * al0 + ps0;
            l1 = l1 * al1 + ps1;
            m0 = mn0; m1 = mn1;
#pragma unroll
            for (int i = 0; i < 16; i++) {
                O[i][0] *= al0; O[i][1] *= al0;
                O[i][2] *= al1; O[i][3] *= al1;
            }

            // ---- O += P V (x3) ----
#pragma unroll
            for (int u = 0; u < 2; u++) {
#pragma unroll
                for (int p = 0; p < 8; p++) {
                    const uint32_t vaddr = kvb + 17408 + (p * 16 + b_n) * AVS + u * 32 + b_kb;
                    uint32_t bh0[2], bh1[2], bl0[2], bl1[2];
                    ldsm_x4(bh0[0], bh0[1], bh1[0], bh1[1], vaddr);
                    ldsm_x4(bl0[0], bl0[1], bl1[0], bl1[1], vaddr + 10240);
                    mma16816(O[2 * p], aPh[u], bh0);
                    mma16816(O[2 * p + 1], aPh[u], bh1);
                    mma16816(O[2 * p], aPl[u], bh0);
                    mma16816(O[2 * p + 1], aPl[u], bh1);
                    mma16816(O[2 * p], aPh[u], bl0);
                    mma16816(O[2 * p + 1], aPh[u], bl1);
                }
            }
        }
        __syncthreads();
    }

    const float inv0 = 1.0f / l0, inv1 = 1.0f / l1;
    const size_t obase = (size_t)(b * TT + qrow0) * DM + h * DH;
#pragma unroll
    for (int ntd = 0; ntd < 16; ntd++) {
        const int d = ntd * 8 + 2 * t2;
        const float v0 = O[ntd][0] * inv0, v1 = O[ntd][1] * inv0;
        const float v2 = O[ntd][2] * inv1, v3 = O[ntd][3] * inv1;
        *(uint32_t*)&g_chi[obase + d] = splitpk_hi(v0, v1);
        *(uint32_t*)&g_clo[obase + d] = splitpk_lo(v0, v1);
        *(uint32_t*)&g_chi[obase + 8 * DM + d] = splitpk_hi(v2, v3);
        *(uint32_t*)&g_clo[obase + 8 * DM + d] = splitpk_lo(v2, v3);
    }
}

// ============================================================
extern "C" void kernel_launch(void* const* d_in, const int* in_sizes, int n_in,
                              void* d_out, int out_size)
{
    const float* x  = (const float*)d_in[0];
    const float* Wq = (const float*)d_in[2];
    const float* bq = (const float*)d_in[3];
    const float* Wk = (const float*)d_in[4];
    const float* bk = (const float*)d_in[5];
    const float* Wv = (const float*)d_in[6];
    const float* bv = (const float*)d_in[7];
    const float* Wo = (const float*)d_in[8];
    const float* bo = (const float*)d_in[9];
    float* out = (float*)d_out;

    const int gsmem = 2 * STG;
    cudaFuncSetAttribute(tc_gemm, cudaFuncAttributeMaxDynamicSharedMemorySize, gsmem);
    cudaFuncSetAttribute(attn_mma, cudaFuncAttributeMaxDynamicSharedMemorySize, ASMEM);

    prep_kernel<<<12800, 256>>>(x, Wq, Wk, Wv, Wo);

    tc_gemm<<<dim3(18, MROWS / 128), 256, gsmem>>>(bq, bk, bv, nullptr, 0, 1);

    vt_kernel<<<dim3(TT / 32, DH / 32, BBAT), 256>>>();

    // 64-row q blocks, 128-thread CTAs, 2 CTAs/SM
    attn_mma<<<dim3(TT / 64, NH, BBAT), 128, ASMEM>>>();

    tc_gemm<<<dim3(16, MROWS / 128), 256, gsmem>>>(bo, nullptr, nullptr, out, 1, 0);
}